// round 8
// baseline (speedup 1.0000x reference)
#include <cuda_runtime.h>
#include <cuda_bf16.h>
#include <math.h>
#include <stdint.h>

#define BATCH  4
#define LSEQ   4096
#define CDIM   512
#define QKVN   (3*CDIM)
#define BLTOT  (BATCH*LSEQ)
#define GROUPS 32
#define EPS_GN 1e-6f
#define EXP_SHIFT 20.0f

// ---- mma.sync GEMM tiling: 256 threads, 8 warps (2m x 4n), warp tile 64x64 ----
#define BM 128
#define BN 256
#define BK 32
#define ROWB    80                     // SMEM row stride bytes (32 bf16 + 8 skew)
#define A_TILE_B (BM*ROWB)             // 10240 B
#define B_TILE_B (BN*ROWB)             // 20480 B
#define STAGE_B  (A_TILE_B + B_TILE_B) // 30720 B
#define NSTAGE 3
#define SMEM_TOTAL (NSTAGE*STAGE_B)    // 92160 B

// ---------------------------------------------------------------------------
// Scratch (static device globals)
// ---------------------------------------------------------------------------
#define DEVBUF static __device__ __align__(16)
DEVBUF __nv_bfloat16 g_xn  [(size_t)BLTOT*CDIM];
DEVBUF __nv_bfloat16 g_qkv [(size_t)BLTOT*QKVN];      // [B*L][1536] q|k|v
DEVBUF __nv_bfloat16 g_vt  [(size_t)BLTOT*CDIM];      // [B][C][L]
DEVBUF __nv_bfloat16 g_ctx [(size_t)BLTOT*CDIM];
DEVBUF __nv_bfloat16 g_pun [(size_t)BATCH*LSEQ*LSEQ]; // 134 MB unnormalized probs
DEVBUF float         g_rowsum[BLTOT];
DEVBUF __nv_bfloat16 g_wqkvT[QKVN*CDIM];              // [1536][512] K-major
DEVBUF __nv_bfloat16 g_woT[CDIM*CDIM];
DEVBUF float         g_bqkv[QKVN];
static __device__ float g_mean[BATCH*GROUPS];
static __device__ float g_rstd[BATCH*GROUPS];

// ---------------------------------------------------------------------------
// PTX helpers
// ---------------------------------------------------------------------------
__device__ __forceinline__ uint32_t smem_u32(const void* p) {
    uint32_t a;
    asm("{ .reg .u64 t; cvta.to.shared.u64 t, %1; cvt.u32.u64 %0, t; }" : "=r"(a) : "l"(p));
    return a;
}
__device__ __forceinline__ void cp16(uint32_t dst, const void* src) {
    asm volatile("cp.async.cg.shared.global [%0], [%1], 16;" :: "r"(dst), "l"(src));
}
#define CP_COMMIT()  asm volatile("cp.async.commit_group;" ::: "memory")
#define CP_WAIT1()   asm volatile("cp.async.wait_group 1;" ::: "memory")
#define CP_WAITALL() asm volatile("cp.async.wait_all;" ::: "memory")

__device__ __forceinline__ void ldsm4(uint32_t* r, uint32_t addr) {
    asm volatile("ldmatrix.sync.aligned.m8n8.x4.shared.b16 {%0,%1,%2,%3}, [%4];"
        : "=r"(r[0]), "=r"(r[1]), "=r"(r[2]), "=r"(r[3]) : "r"(addr));
}
__device__ __forceinline__ void mma16816(float* c, const uint32_t* a, const uint32_t* b) {
    asm volatile("mma.sync.aligned.m16n8k16.row.col.f32.bf16.bf16.f32 "
        "{%0,%1,%2,%3}, {%4,%5,%6,%7}, {%8,%9}, {%0,%1,%2,%3};"
        : "+f"(c[0]), "+f"(c[1]), "+f"(c[2]), "+f"(c[3])
        : "r"(a[0]), "r"(a[1]), "r"(a[2]), "r"(a[3]), "r"(b[0]), "r"(b[1]));
}
__device__ __forceinline__ uint32_t pack_bf16(float a, float b) {
    return (uint32_t)__bfloat16_as_ushort(__float2bfloat16(a)) |
           ((uint32_t)__bfloat16_as_ushort(__float2bfloat16(b)) << 16);
}

// ---------------------------------------------------------------------------
// GroupNorm stats
// ---------------------------------------------------------------------------
__global__ void __launch_bounds__(256) gn_stats_kernel(const float* __restrict__ x) {
    int b = blockIdx.x / GROUPS, g = blockIdx.x % GROUPS;
    const float* base = x + (size_t)b * LSEQ * CDIM + g * 16;
    float s = 0.f, s2 = 0.f;
    for (int l = threadIdx.x; l < LSEQ; l += 256) {
        const float4* p = (const float4*)(base + (size_t)l * CDIM);
        #pragma unroll
        for (int j = 0; j < 4; ++j) {
            float4 v = p[j];
            s  += v.x + v.y + v.z + v.w;
            s2 += v.x*v.x + v.y*v.y + v.z*v.z + v.w*v.w;
        }
    }
    __shared__ float sh1[256], sh2[256];
    sh1[threadIdx.x] = s; sh2[threadIdx.x] = s2;
    __syncthreads();
    for (int st = 128; st > 0; st >>= 1) {
        if (threadIdx.x < st) { sh1[threadIdx.x] += sh1[threadIdx.x+st]; sh2[threadIdx.x] += sh2[threadIdx.x+st]; }
        __syncthreads();
    }
    if (threadIdx.x == 0) {
        const float inv = 1.f / (float)(LSEQ * 16);
        float m = sh1[0] * inv;
        g_mean[blockIdx.x] = m;
        g_rstd[blockIdx.x] = rsqrtf(sh2[0]*inv - m*m + EPS_GN);
    }
}

// ---------------------------------------------------------------------------
// Normalize + affine -> bf16 xn
// ---------------------------------------------------------------------------
__global__ void __launch_bounds__(256) gn_norm_bf16(const float* __restrict__ x,
                                                    const float* __restrict__ w,
                                                    const float* __restrict__ bb) {
    size_t i = ((size_t)blockIdx.x * 256 + threadIdx.x) * 4;
    int c = (int)(i & (CDIM - 1));
    int b = (int)(i >> 21);
    int gidx = b * GROUPS + (c >> 4);
    float m = g_mean[gidx], r = g_rstd[gidx];
    float4 v  = *(const float4*)(x + i);
    float4 gw = *(const float4*)(w + c);
    float4 gb = *(const float4*)(bb + c);
    uint2 hv;
    hv.x = pack_bf16((v.x-m)*r*gw.x + gb.x, (v.y-m)*r*gw.y + gb.y);
    hv.y = pack_bf16((v.z-m)*r*gw.z + gb.z, (v.w-m)*r*gw.w + gb.w);
    *(uint2*)(g_xn + i) = hv;
}

// ---------------------------------------------------------------------------
// Transpose fp32 -> bf16 (weights) into K-major [n][k] at given output base
// ---------------------------------------------------------------------------
__global__ void transpose_f2b(const float* __restrict__ in,
                              __nv_bfloat16* __restrict__ oh,
                              int rows, int cols) {
    __shared__ float t[32][33];
    int c0 = blockIdx.x * 32, r0 = blockIdx.y * 32;
    for (int dy = threadIdx.y; dy < 32; dy += 8)
        t[dy][threadIdx.x] = in[(size_t)(r0 + dy) * cols + c0 + threadIdx.x];
    __syncthreads();
    for (int dy = threadIdx.y; dy < 32; dy += 8)
        oh[(size_t)(c0 + dy) * rows + r0 + threadIdx.x] = __float2bfloat16(t[threadIdx.x][dy]);
}

// ---------------------------------------------------------------------------
// Transpose bf16 -> bf16 (V slice of qkv): out[z][c][r] = in[z][r][c]
// ---------------------------------------------------------------------------
__global__ void transpose_b2b(const __nv_bfloat16* __restrict__ in,
                              __nv_bfloat16* __restrict__ oh,
                              int rows, int ldIn, size_t strideIn, size_t strideOut) {
    __shared__ unsigned short t[32][33];
    int c0 = blockIdx.x * 32, r0 = blockIdx.y * 32, z = blockIdx.z;
    const __nv_bfloat16* I = in + (size_t)z * strideIn;
    for (int dy = threadIdx.y; dy < 32; dy += 8)
        t[dy][threadIdx.x] = __bfloat16_as_ushort(I[(size_t)(r0 + dy) * ldIn + c0 + threadIdx.x]);
    __syncthreads();
    for (int dy = threadIdx.y; dy < 32; dy += 8) {
        size_t o = (size_t)z * strideOut + (size_t)(c0 + dy) * rows + r0 + threadIdx.x;
        oh[o] = __ushort_as_bfloat16(t[threadIdx.x][dy]);
    }
}

// ---------------------------------------------------------------------------
// Setup: zero rowsum + combined qkv bias
// ---------------------------------------------------------------------------
__global__ void setup_kernel(const float* bq, const float* bk, const float* bv) {
    int t = blockIdx.x * 256 + threadIdx.x;
    if (t < BLTOT) g_rowsum[t] = 0.f;
    if (t < CDIM) {
        g_bqkv[t]          = bq[t];
        g_bqkv[t + CDIM]   = bk[t];
        g_bqkv[t + 2*CDIM] = bv[t];
    }
}

// ---------------------------------------------------------------------------
// bf16 GEMM via mma.sync: D[M,N] = A @ B^T variants.
//   OUTMODE 0: fp32 out, alpha, +bias, +resid         (output projection)
//   OUTMODE 1: bf16 out, +bias                        (QKV projection)
//   OUTMODE 2: bf16 exp(alpha*s - SHIFT) out + rowsum (scores -> unnorm P)
//   OUTMODE 3: bf16 out scaled by 1/rowsum[row]       (P @ V)
// 256 threads, warps 2(m) x 4(n), warp tile 64x64, 3-stage cp.async.
// ---------------------------------------------------------------------------
__device__ __forceinline__ void load_stage(
    uint32_t sbase,
    const __nv_bfloat16* __restrict__ A, const __nv_bfloat16* __restrict__ B,
    int row0, int col0, int kk, int ldA, int ldB, int tid)
{
    #pragma unroll
    for (int j = 0; j < 2; ++j) {      // A: 128 rows x 32 cols = 512 cp16
        int idx = tid + 256*j;
        int r = idx >> 2, k16 = idx & 3;
        cp16(sbase + (uint32_t)(r*ROWB + k16*16),
             A + (size_t)(row0 + r) * ldA + kk + k16*8);
    }
    #pragma unroll
    for (int j = 0; j < 4; ++j) {      // B: 256 rows x 32 cols = 1024 cp16
        int idx = tid + 256*j;
        int r = idx >> 2, k16 = idx & 3;
        cp16(sbase + A_TILE_B + (uint32_t)(r*ROWB + k16*16),
             B + (size_t)(col0 + r) * ldB + kk + k16*8);
    }
}

template<int OUTMODE>
__global__ void __launch_bounds__(256, 1) mma_gemm(
    const __nv_bfloat16* __restrict__ A, const __nv_bfloat16* __restrict__ B,
    float* __restrict__ Cf, __nv_bfloat16* __restrict__ Cb,
    float* __restrict__ rowsum,
    int K, int ldA, int ldB, int ldC,
    size_t sA, size_t sB, size_t sC,
    float alpha, const float* __restrict__ bias, const float* __restrict__ resid)
{
    extern __shared__ __align__(128) char smem[];
    const uint32_t sb0 = smem_u32(smem);
    const int tid = threadIdx.x;
    const int lane = tid & 31, wid = tid >> 5;
    const int wm = wid & 1, wn = wid >> 1;        // warps 2(m) x 4(n)
    const int row0 = blockIdx.y * BM;
    const int col0 = blockIdx.x * BN;
    A += sA * blockIdx.z; B += sB * blockIdx.z;
    const size_t zC = sC * blockIdx.z;
    float* rsumz = rowsum + (size_t)blockIdx.z * LSEQ;

    const int g = lane >> 3, r = lane & 7;
    const uint32_t aoff = (uint32_t)((wm*64 + (g&1)*8 + r) * ROWB + (g>>1)*16);
    const uint32_t boff = (uint32_t)((wn*64 + (g>>1)*8 + r) * ROWB + (g&1)*16);

    float acc[4][8][4];
    #pragma unroll
    for (int a1 = 0; a1 < 4; ++a1)
        #pragma unroll
        for (int a2 = 0; a2 < 8; ++a2)
            #pragma unroll
            for (int a3 = 0; a3 < 4; ++a3) acc[a1][a2][a3] = 0.f;

    const int nch = K / BK;
    load_stage(sb0,           A, B, row0, col0, 0,  ldA, ldB, tid); CP_COMMIT();
    load_stage(sb0 + STAGE_B, A, B, row0, col0, BK, ldA, ldB, tid); CP_COMMIT();

    int slot = 0;
    for (int i = 0; i < nch; ++i) {
        CP_WAIT1();
        __syncthreads();
        const int nxt = i + 2;
        if (nxt < nch) {
            int ns = nxt - (nxt / NSTAGE) * NSTAGE;
            load_stage(sb0 + (uint32_t)(ns * STAGE_B),
                       A, B, row0, col0, nxt * BK, ldA, ldB, tid);
        }
        CP_COMMIT();

        const uint32_t sb = sb0 + (uint32_t)(slot * STAGE_B);
        if (++slot == NSTAGE) slot = 0;
        #pragma unroll
        for (int ks = 0; ks < 2; ++ks) {
            uint32_t ah[4][4], bh[4][4];
            #pragma unroll
            for (int mf = 0; mf < 4; ++mf)
                ldsm4(ah[mf], sb + aoff + (uint32_t)(mf*(16*ROWB) + ks*32));
            #pragma unroll
            for (int nf = 0; nf < 4; ++nf)
                ldsm4(bh[nf], sb + A_TILE_B + boff + (uint32_t)(nf*(16*ROWB) + ks*32));
            #pragma unroll
            for (int mf = 0; mf < 4; ++mf)
                #pragma unroll
                for (int nf = 0; nf < 4; ++nf)
                    #pragma unroll
                    for (int n8 = 0; n8 < 2; ++n8)
                        mma16816(acc[mf][nf*2 + n8], ah[mf], &bh[nf][n8*2]);
        }
    }

    // ---- epilogue ----
    float rs[4][2];
    float* srow = (float*)smem;
    if (OUTMODE == 2) {
        #pragma unroll
        for (int mf = 0; mf < 4; ++mf) rs[mf][0] = rs[mf][1] = 0.f;
        CP_WAITALL();
        __syncthreads();
        if (tid < BM) srow[tid] = 0.f;
        __syncthreads();
    }

    float inv0[4], inv1[4];
    if (OUTMODE == 3) {
        #pragma unroll
        for (int mf = 0; mf < 4; ++mf) {
            int rl = row0 + wm*64 + mf*16 + (lane >> 2);
            inv0[mf] = 1.f / rsumz[rl];
            inv1[mf] = 1.f / rsumz[rl + 8];
        }
    }

    #pragma unroll
    for (int mf = 0; mf < 4; ++mf) {
        #pragma unroll
        for (int nf = 0; nf < 4; ++nf) {
            #pragma unroll
            for (int n8 = 0; n8 < 2; ++n8) {
                float* c = acc[mf][nf*2 + n8];
                const int col = col0 + wn*64 + nf*16 + n8*8 + 2*(lane & 3);
                const int rlo = row0 + wm*64 + mf*16 + (lane >> 2);
                const size_t o0 = zC + (size_t)rlo * ldC + col;
                const size_t o1 = zC + (size_t)(rlo + 8) * ldC + col;
                if (OUTMODE == 2) {
                    float e0 = __expf(fmaf(c[0], alpha, -EXP_SHIFT));
                    float e1 = __expf(fmaf(c[1], alpha, -EXP_SHIFT));
                    float e2 = __expf(fmaf(c[2], alpha, -EXP_SHIFT));
                    float e3 = __expf(fmaf(c[3], alpha, -EXP_SHIFT));
                    rs[mf][0] += e0 + e1;
                    rs[mf][1] += e2 + e3;
                    *(uint32_t*)(Cb + o0) = pack_bf16(e0, e1);
                    *(uint32_t*)(Cb + o1) = pack_bf16(e2, e3);
                } else if (OUTMODE == 3) {
                    *(uint32_t*)(Cb + o0) = pack_bf16(c[0]*inv0[mf], c[1]*inv0[mf]);
                    *(uint32_t*)(Cb + o1) = pack_bf16(c[2]*inv1[mf], c[3]*inv1[mf]);
                } else {
                    float v0 = c[0], v1 = c[1], v2 = c[2], v3 = c[3];
                    if (bias) {
                        float b0 = bias[col], b1 = bias[col+1];
                        v0 += b0; v1 += b1; v2 += b0; v3 += b1;
                    }
                    if (OUTMODE == 0) {
                        if (resid) {
                            float2 r0v = *(const float2*)(resid + o0);
                            float2 r1v = *(const float2*)(resid + o1);
                            v0 += r0v.x; v1 += r0v.y; v2 += r1v.x; v3 += r1v.y;
                        }
                        *(float2*)(Cf + o0) = make_float2(v0, v1);
                        *(float2*)(Cf + o1) = make_float2(v2, v3);
                    } else {
                        *(uint32_t*)(Cb + o0) = pack_bf16(v0, v1);
                        *(uint32_t*)(Cb + o1) = pack_bf16(v2, v3);
                    }
                }
            }
        }
    }

    if (OUTMODE == 2) {
        #pragma unroll
        for (int mf = 0; mf < 4; ++mf)
            #pragma unroll
            for (int h = 0; h < 2; ++h) {
                rs[mf][h] += __shfl_xor_sync(0xffffffffu, rs[mf][h], 1);
                rs[mf][h] += __shfl_xor_sync(0xffffffffu, rs[mf][h], 2);
            }
        if ((lane & 3) == 0) {
            int lr = wm*64 + (lane >> 2);
            #pragma unroll
            for (int mf = 0; mf < 4; ++mf) {
                atomicAdd(&srow[lr + mf*16],     rs[mf][0]);
                atomicAdd(&srow[lr + mf*16 + 8], rs[mf][1]);
            }
        }
        __syncthreads();
        if (tid < BM) atomicAdd(&rsumz[row0 + tid], srow[tid]);
    }
}

// ---------------------------------------------------------------------------
// Launch
// ---------------------------------------------------------------------------
#define SYM(p, s) do { void* _t = nullptr; cudaGetSymbolAddress(&_t, s); p = (decltype(p))_t; } while (0)

extern "C" void kernel_launch(void* const* d_in, const int* in_sizes, int n_in,
                              void* d_out, int out_size) {
    const float* x   = (const float*)d_in[0];
    const float* gnw = (const float*)d_in[1];
    const float* gnb = (const float*)d_in[2];
    const float* wq  = (const float*)d_in[3];
    const float* bq  = (const float*)d_in[4];
    const float* wk  = (const float*)d_in[5];
    const float* bk  = (const float*)d_in[6];
    const float* wv  = (const float*)d_in[7];
    const float* bv  = (const float*)d_in[8];
    const float* wo  = (const float*)d_in[9];
    const float* bo  = (const float*)d_in[10];
    float* out = (float*)d_out;

    cudaFuncSetAttribute(mma_gemm<0>, cudaFuncAttributeMaxDynamicSharedMemorySize, SMEM_TOTAL);
    cudaFuncSetAttribute(mma_gemm<1>, cudaFuncAttributeMaxDynamicSharedMemorySize, SMEM_TOTAL);
    cudaFuncSetAttribute(mma_gemm<2>, cudaFuncAttributeMaxDynamicSharedMemorySize, SMEM_TOTAL);
    cudaFuncSetAttribute(mma_gemm<3>, cudaFuncAttributeMaxDynamicSharedMemorySize, SMEM_TOTAL);

    __nv_bfloat16 *xn,*qkv,*vt,*cx,*pun,*wqkvT,*woT;
    float *rsum, *bqkv;
    SYM(xn,  g_xn);     SYM(qkv, g_qkv);  SYM(vt, g_vt);
    SYM(cx,  g_ctx);    SYM(pun, g_pun);
    SYM(rsum, g_rowsum); SYM(bqkv, g_bqkv);
    SYM(wqkvT, g_wqkvT); SYM(woT, g_woT);

    const size_t LQKV = (size_t)LSEQ * QKVN;  // per-batch qkv stride
    const size_t LC   = (size_t)LSEQ * CDIM;
    const size_t LL   = (size_t)LSEQ * LSEQ;
    const float attn_scale = 1.f / sqrtf((float)CDIM);

    // 1) GroupNorm -> bf16 xn ; setup (rowsum zero + combined bias)
    gn_stats_kernel<<<BATCH * GROUPS, 256>>>(x);
    gn_norm_bf16<<<8192, 256>>>(x, gnw, gnb);
    setup_kernel<<<BLTOT/256, 256>>>(bq, bk, bv);

    // 2) transpose weights into combined [1536][512] K-major
    dim3 tw(32, 8);
    dim3 gw(CDIM/32, CDIM/32, 1);
    transpose_f2b<<<gw, tw>>>(wq, wqkvT,            CDIM, CDIM);
    transpose_f2b<<<gw, tw>>>(wk, wqkvT + CDIM*CDIM,  CDIM, CDIM);
    transpose_f2b<<<gw, tw>>>(wv, wqkvT + 2*CDIM*CDIM, CDIM, CDIM);
    transpose_f2b<<<gw, tw>>>(wo, woT, CDIM, CDIM);

    // 3) fused QKV projection: [16384,512] x [1536,512]^T -> [16384,1536]
    dim3 grid_qkv(QKVN/BN, BLTOT/BM, 1);
    mma_gemm<1><<<grid_qkv, 256, SMEM_TOTAL>>>(xn, wqkvT, nullptr, qkv, nullptr,
        CDIM, CDIM, CDIM, QKVN, 0, 0, 0, 1.f, bqkv, nullptr);

    // 4) V^T from qkv slice (cols 1024..1535): vt[b][c][l]
    transpose_b2b<<<dim3(CDIM/32, LSEQ/32, BATCH), tw>>>(
        qkv + 2*CDIM, vt, LSEQ, QKVN, LQKV, LC);

    // 5) unnormalized P = exp(scale*Q@K^T - SHIFT), accumulate row sums
    dim3 grid_s(LSEQ/BN, LSEQ/BM, BATCH);
    mma_gemm<2><<<grid_s, 256, SMEM_TOTAL>>>(qkv, qkv + CDIM, nullptr, pun, rsum,
        CDIM, QKVN, QKVN, LSEQ, LQKV, LQKV, LL, attn_scale, nullptr, nullptr);

    // 6) ctx = (P_un @ V) / rowsum
    dim3 grid_pv(CDIM/BN, LSEQ/BM, BATCH);
    mma_gemm<3><<<grid_pv, 256, SMEM_TOTAL>>>(pun, vt, nullptr, cx, rsum,
        LSEQ, LSEQ, LSEQ, CDIM, LL, LC, LC, 1.f, nullptr, nullptr);

    // 7) out = ctx @ wo^T + bo + residual
    dim3 grid_o(CDIM/BN, BLTOT/BM, 1);
    mma_gemm<0><<<grid_o, 256, SMEM_TOTAL>>>(cx, woT, out, nullptr, nullptr,
        CDIM, CDIM, CDIM, CDIM, 0, 0, 0, 1.f, bo, x);
}

// round 11
// speedup vs baseline: 1.0700x; 1.0700x over previous
#include <cuda_runtime.h>
#include <cuda_bf16.h>
#include <math.h>
#include <stdint.h>

#define BATCH  4
#define LSEQ   4096
#define CDIM   512
#define QKVN   (3*CDIM)
#define BLTOT  (BATCH*LSEQ)
#define GROUPS 32
#define EPS_GN 1e-6f
#define EXP_SHIFT 20.0f

// ---- mma.sync GEMM tiling: 512 threads, 16 warps (4m x 4n), warp tile 32x64 ----
#define BM 128
#define BN 256
#define BK 32
#define ROWB    80                     // SMEM row stride bytes (32 bf16 + 8 skew)
#define A_TILE_B (BM*ROWB)             // 10240 B
#define B_TILE_B (BN*ROWB)             // 20480 B
#define STAGE_B  (A_TILE_B + B_TILE_B) // 30720 B
#define NSTAGE 5
#define SMEM_TOTAL (NSTAGE*STAGE_B)    // 153600 B

// ---------------------------------------------------------------------------
// Scratch (static device globals)
// ---------------------------------------------------------------------------
#define DEVBUF static __device__ __align__(16)
DEVBUF __nv_bfloat16 g_xn  [(size_t)BLTOT*CDIM];
DEVBUF __nv_bfloat16 g_qkv [(size_t)BLTOT*QKVN];      // [B*L][1536] q|k|v
DEVBUF __nv_bfloat16 g_vwo [(size_t)BLTOT*CDIM];      // V @ Wo  [B*L][C]
DEVBUF __nv_bfloat16 g_vwt [(size_t)BLTOT*CDIM];      // (V@Wo)^T [B][C][L]
DEVBUF __nv_bfloat16 g_pun [(size_t)BATCH*LSEQ*LSEQ]; // 134 MB unnormalized probs
DEVBUF float         g_rowsum[BLTOT];
DEVBUF __nv_bfloat16 g_wqkvT[QKVN*CDIM];              // [1536][512] K-major
DEVBUF __nv_bfloat16 g_woT[CDIM*CDIM];
DEVBUF float         g_bqkv[QKVN];
static __device__ float g_mean[BATCH*GROUPS];
static __device__ float g_rstd[BATCH*GROUPS];

// ---------------------------------------------------------------------------
// PTX helpers
// ---------------------------------------------------------------------------
__device__ __forceinline__ uint32_t smem_u32(const void* p) {
    uint32_t a;
    asm("{ .reg .u64 t; cvta.to.shared.u64 t, %1; cvt.u32.u64 %0, t; }" : "=r"(a) : "l"(p));
    return a;
}
__device__ __forceinline__ void cp16(uint32_t dst, const void* src) {
    asm volatile("cp.async.cg.shared.global [%0], [%1], 16;" :: "r"(dst), "l"(src));
}
#define CP_COMMIT()  asm volatile("cp.async.commit_group;" ::: "memory")
#define CP_WAIT3()   asm volatile("cp.async.wait_group 3;" ::: "memory")
#define CP_WAITALL() asm volatile("cp.async.wait_all;" ::: "memory")

__device__ __forceinline__ void ldsm4(uint32_t* r, uint32_t addr) {
    asm volatile("ldmatrix.sync.aligned.m8n8.x4.shared.b16 {%0,%1,%2,%3}, [%4];"
        : "=r"(r[0]), "=r"(r[1]), "=r"(r[2]), "=r"(r[3]) : "r"(addr));
}
__device__ __forceinline__ void mma16816(float* c, const uint32_t* a, const uint32_t* b) {
    asm volatile("mma.sync.aligned.m16n8k16.row.col.f32.bf16.bf16.f32 "
        "{%0,%1,%2,%3}, {%4,%5,%6,%7}, {%8,%9}, {%0,%1,%2,%3};"
        : "+f"(c[0]), "+f"(c[1]), "+f"(c[2]), "+f"(c[3])
        : "r"(a[0]), "r"(a[1]), "r"(a[2]), "r"(a[3]), "r"(b[0]), "r"(b[1]));
}
__device__ __forceinline__ uint32_t pack_bf16(float a, float b) {
    return (uint32_t)__bfloat16_as_ushort(__float2bfloat16(a)) |
           ((uint32_t)__bfloat16_as_ushort(__float2bfloat16(b)) << 16);
}

// ---------------------------------------------------------------------------
// GroupNorm stats
// ---------------------------------------------------------------------------
__global__ void __launch_bounds__(256) gn_stats_kernel(const float* __restrict__ x) {
    int b = blockIdx.x / GROUPS, g = blockIdx.x % GROUPS;
    const float* base = x + (size_t)b * LSEQ * CDIM + g * 16;
    float s = 0.f, s2 = 0.f;
    for (int l = threadIdx.x; l < LSEQ; l += 256) {
        const float4* p = (const float4*)(base + (size_t)l * CDIM);
        #pragma unroll
        for (int j = 0; j < 4; ++j) {
            float4 v = p[j];
            s  += v.x + v.y + v.z + v.w;
            s2 += v.x*v.x + v.y*v.y + v.z*v.z + v.w*v.w;
        }
    }
    __shared__ float sh1[256], sh2[256];
    sh1[threadIdx.x] = s; sh2[threadIdx.x] = s2;
    __syncthreads();
    for (int st = 128; st > 0; st >>= 1) {
        if (threadIdx.x < st) { sh1[threadIdx.x] += sh1[threadIdx.x+st]; sh2[threadIdx.x] += sh2[threadIdx.x+st]; }
        __syncthreads();
    }
    if (threadIdx.x == 0) {
        const float inv = 1.f / (float)(LSEQ * 16);
        float m = sh1[0] * inv;
        g_mean[blockIdx.x] = m;
        g_rstd[blockIdx.x] = rsqrtf(sh2[0]*inv - m*m + EPS_GN);
    }
}

// ---------------------------------------------------------------------------
// Normalize + affine -> bf16 xn
// ---------------------------------------------------------------------------
__global__ void __launch_bounds__(256) gn_norm_bf16(const float* __restrict__ x,
                                                    const float* __restrict__ w,
                                                    const float* __restrict__ bb) {
    size_t i = ((size_t)blockIdx.x * 256 + threadIdx.x) * 4;
    int c = (int)(i & (CDIM - 1));
    int b = (int)(i >> 21);
    int gidx = b * GROUPS + (c >> 4);
    float m = g_mean[gidx], r = g_rstd[gidx];
    float4 v  = *(const float4*)(x + i);
    float4 gw = *(const float4*)(w + c);
    float4 gb = *(const float4*)(bb + c);
    uint2 hv;
    hv.x = pack_bf16((v.x-m)*r*gw.x + gb.x, (v.y-m)*r*gw.y + gb.y);
    hv.y = pack_bf16((v.z-m)*r*gw.z + gb.z, (v.w-m)*r*gw.w + gb.w);
    *(uint2*)(g_xn + i) = hv;
}

// ---------------------------------------------------------------------------
// Transpose fp32 -> bf16 (weights) into K-major [n][k]
// ---------------------------------------------------------------------------
__global__ void transpose_f2b(const float* __restrict__ in,
                              __nv_bfloat16* __restrict__ oh,
                              int rows, int cols) {
    __shared__ float t[32][33];
    int c0 = blockIdx.x * 32, r0 = blockIdx.y * 32;
    for (int dy = threadIdx.y; dy < 32; dy += 8)
        t[dy][threadIdx.x] = in[(size_t)(r0 + dy) * cols + c0 + threadIdx.x];
    __syncthreads();
    for (int dy = threadIdx.y; dy < 32; dy += 8)
        oh[(size_t)(c0 + dy) * rows + r0 + threadIdx.x] = __float2bfloat16(t[threadIdx.x][dy]);
}

// ---------------------------------------------------------------------------
// Transpose bf16 -> bf16: out[z][c][r] = in[z][r][c]
// ---------------------------------------------------------------------------
__global__ void transpose_b2b(const __nv_bfloat16* __restrict__ in,
                              __nv_bfloat16* __restrict__ oh,
                              int rows, int ldIn, size_t strideIn, size_t strideOut) {
    __shared__ unsigned short t[32][33];
    int c0 = blockIdx.x * 32, r0 = blockIdx.y * 32, z = blockIdx.z;
    const __nv_bfloat16* I = in + (size_t)z * strideIn;
    for (int dy = threadIdx.y; dy < 32; dy += 8)
        t[dy][threadIdx.x] = __bfloat16_as_ushort(I[(size_t)(r0 + dy) * ldIn + c0 + threadIdx.x]);
    __syncthreads();
    for (int dy = threadIdx.y; dy < 32; dy += 8) {
        size_t o = (size_t)z * strideOut + (size_t)(c0 + dy) * rows + r0 + threadIdx.x;
        oh[o] = __ushort_as_bfloat16(t[threadIdx.x][dy]);
    }
}

// ---------------------------------------------------------------------------
// Setup: zero rowsum + combined qkv bias
// ---------------------------------------------------------------------------
__global__ void setup_kernel(const float* bq, const float* bk, const float* bv) {
    int t = blockIdx.x * 256 + threadIdx.x;
    if (t < BLTOT) g_rowsum[t] = 0.f;
    if (t < CDIM) {
        g_bqkv[t]          = bq[t];
        g_bqkv[t + CDIM]   = bk[t];
        g_bqkv[t + 2*CDIM] = bv[t];
    }
}

// ---------------------------------------------------------------------------
// bf16 GEMM via mma.sync: D[M,N] = A @ B^T variants.
//   OUTMODE 0: fp32 out, x (1/rowsum[row]), +bias, +resid  (final P@VWo)
//   OUTMODE 1: bf16 out, optional +bias                    (QKV / VWo)
//   OUTMODE 2: bf16 exp(alpha*s - SHIFT) out + rowsum      (scores)
// 512 threads, warps 4(m) x 4(n), warp tile 32x64, 5-stage cp.async.
// ---------------------------------------------------------------------------
__device__ __forceinline__ void load_stage(
    uint32_t sbase,
    const __nv_bfloat16* __restrict__ A, const __nv_bfloat16* __restrict__ B,
    int row0, int col0, int kk, int ldA, int ldB, int tid)
{
    {
        int r = tid >> 2, k16 = tid & 3;
        cp16(sbase + (uint32_t)(r*ROWB + k16*16),
             A + (size_t)(row0 + r) * ldA + kk + k16*8);
    }
    #pragma unroll
    for (int j = 0; j < 2; ++j) {
        int idx = tid + 512*j;
        int r = idx >> 2, k16 = idx & 3;
        cp16(sbase + A_TILE_B + (uint32_t)(r*ROWB + k16*16),
             B + (size_t)(col0 + r) * ldB + kk + k16*8);
    }
}

template<int OUTMODE>
__global__ void __launch_bounds__(512, 1) mma_gemm(
    const __nv_bfloat16* __restrict__ A, const __nv_bfloat16* __restrict__ B,
    float* __restrict__ Cf, __nv_bfloat16* __restrict__ Cb,
    float* __restrict__ rowsum,
    int K, int ldA, int ldB, int ldC,
    size_t sA, size_t sB, size_t sC,
    float alpha, const float* __restrict__ bias, const float* __restrict__ resid)
{
    extern __shared__ __align__(128) char smem[];
    const uint32_t sb0 = smem_u32(smem);
    const int tid = threadIdx.x;
    const int lane = tid & 31, wid = tid >> 5;
    const int wm = wid & 3, wn = wid >> 2;        // warps 4(m) x 4(n)
    const int row0 = blockIdx.y * BM;
    const int col0 = blockIdx.x * BN;
    A += sA * blockIdx.z; B += sB * blockIdx.z;
    const size_t zC = sC * blockIdx.z;
    float* rsumz = rowsum ? rowsum + (size_t)blockIdx.z * LSEQ : nullptr;

    const int g = lane >> 3, r = lane & 7;
    const uint32_t aoff = (uint32_t)((wm*32 + (g&1)*8 + r) * ROWB + (g>>1)*16);
    const uint32_t boff = (uint32_t)((wn*64 + (g>>1)*8 + r) * ROWB + (g&1)*16);

    float acc[2][8][4];
    #pragma unroll
    for (int a1 = 0; a1 < 2; ++a1)
        #pragma unroll
        for (int a2 = 0; a2 < 8; ++a2)
            #pragma unroll
            for (int a3 = 0; a3 < 4; ++a3) acc[a1][a2][a3] = 0.f;

    const int nch = K / BK;
    load_stage(sb0,             A, B, row0, col0, 0,    ldA, ldB, tid); CP_COMMIT();
    load_stage(sb0 + STAGE_B,   A, B, row0, col0, BK,   ldA, ldB, tid); CP_COMMIT();
    load_stage(sb0 + 2*STAGE_B, A, B, row0, col0, 2*BK, ldA, ldB, tid); CP_COMMIT();
    load_stage(sb0 + 3*STAGE_B, A, B, row0, col0, 3*BK, ldA, ldB, tid); CP_COMMIT();

    int cslot = 0, lslot = 4;
    for (int i = 0; i < nch; ++i) {
        CP_WAIT3();
        __syncthreads();
        const int nxt = i + 4;
        if (nxt < nch) {
            load_stage(sb0 + (uint32_t)(lslot * STAGE_B),
                       A, B, row0, col0, nxt * BK, ldA, ldB, tid);
            if (++lslot == NSTAGE) lslot = 0;
        }
        CP_COMMIT();

        const uint32_t sb = sb0 + (uint32_t)(cslot * STAGE_B);
        if (++cslot == NSTAGE) cslot = 0;
        #pragma unroll
        for (int ks = 0; ks < 2; ++ks) {
            uint32_t ah[2][4], bh[4][4];
            #pragma unroll
            for (int mf = 0; mf < 2; ++mf)
                ldsm4(ah[mf], sb + aoff + (uint32_t)(mf*(16*ROWB) + ks*32));
            #pragma unroll
            for (int nf = 0; nf < 4; ++nf)
                ldsm4(bh[nf], sb + A_TILE_B + boff + (uint32_t)(nf*(16*ROWB) + ks*32));
            #pragma unroll
            for (int mf = 0; mf < 2; ++mf)
                #pragma unroll
                for (int nf = 0; nf < 4; ++nf)
                    #pragma unroll
                    for (int n8 = 0; n8 < 2; ++n8)
                        mma16816(acc[mf][nf*2 + n8], ah[mf], &bh[nf][n8*2]);
        }
    }

    // ---- epilogue ----
    float rs[2][2];
    float* srow = (float*)smem;
    if (OUTMODE == 2) {
        rs[0][0] = rs[0][1] = rs[1][0] = rs[1][1] = 0.f;
        CP_WAITALL();
        __syncthreads();
        if (tid < BM) srow[tid] = 0.f;
        __syncthreads();
    }

    float inv0[2], inv1[2];
    if (OUTMODE == 0) {
        #pragma unroll
        for (int mf = 0; mf < 2; ++mf) {
            int rl = row0 + wm*32 + mf*16 + (lane >> 2);
            inv0[mf] = 1.f / rsumz[rl];
            inv1[mf] = 1.f / rsumz[rl + 8];
        }
    }

    #pragma unroll
    for (int mf = 0; mf < 2; ++mf) {
        #pragma unroll
        for (int nf = 0; nf < 4; ++nf) {
            #pragma unroll
            for (int n8 = 0; n8 < 2; ++n8) {
                float* c = acc[mf][nf*2 + n8];
                const int col = col0 + wn*64 + nf*16 + n8*8 + 2*(lane & 3);
                const int rlo = row0 + wm*32 + mf*16 + (lane >> 2);
                const size_t o0 = zC + (size_t)rlo * ldC + col;
                const size_t o1 = zC + (size_t)(rlo + 8) * ldC + col;
                if (OUTMODE == 2) {
                    float e0 = __expf(fmaf(c[0], alpha, -EXP_SHIFT));
                    float e1 = __expf(fmaf(c[1], alpha, -EXP_SHIFT));
                    float e2 = __expf(fmaf(c[2], alpha, -EXP_SHIFT));
                    float e3 = __expf(fmaf(c[3], alpha, -EXP_SHIFT));
                    rs[mf][0] += e0 + e1;
                    rs[mf][1] += e2 + e3;
                    *(uint32_t*)(Cb + o0) = pack_bf16(e0, e1);
                    *(uint32_t*)(Cb + o1) = pack_bf16(e2, e3);
                } else if (OUTMODE == 0) {
                    float b0 = bias[col], b1 = bias[col+1];
                    float2 r0v = *(const float2*)(resid + o0);
                    float2 r1v = *(const float2*)(resid + o1);
                    float v0 = fmaf(c[0], inv0[mf], b0 + r0v.x);
                    float v1 = fmaf(c[1], inv0[mf], b1 + r0v.y);
                    float v2 = fmaf(c[2], inv1[mf], b0 + r1v.x);
                    float v3 = fmaf(c[3], inv1[mf], b1 + r1v.y);
                    *(float2*)(Cf + o0) = make_float2(v0, v1);
                    *(float2*)(Cf + o1) = make_float2(v2, v3);
                } else {
                    float v0 = c[0], v1 = c[1], v2 = c[2], v3 = c[3];
                    if (bias) {
                        float b0 = bias[col], b1 = bias[col+1];
                        v0 += b0; v1 += b1; v2 += b0; v3 += b1;
                    }
                    *(uint32_t*)(Cb + o0) = pack_bf16(v0, v1);
                    *(uint32_t*)(Cb + o1) = pack_bf16(v2, v3);
                }
            }
        }
    }

    if (OUTMODE == 2) {
        #pragma unroll
        for (int mf = 0; mf < 2; ++mf)
            #pragma unroll
            for (int h = 0; h < 2; ++h) {
                rs[mf][h] += __shfl_xor_sync(0xffffffffu, rs[mf][h], 1);
                rs[mf][h] += __shfl_xor_sync(0xffffffffu, rs[mf][h], 2);
            }
        if ((lane & 3) == 0) {
            int lr = wm*32 + (lane >> 2);
            #pragma unroll
            for (int mf = 0; mf < 2; ++mf) {
                atomicAdd(&srow[lr + mf*16],     rs[mf][0]);
                atomicAdd(&srow[lr + mf*16 + 8], rs[mf][1]);
            }
        }
        __syncthreads();
        if (tid < BM) atomicAdd(&rsumz[row0 + tid], srow[tid]);
    }
}

// ---------------------------------------------------------------------------
// Launch
// ---------------------------------------------------------------------------
#define SYM(p, s) do { void* _t = nullptr; cudaGetSymbolAddress(&_t, s); p = (decltype(p))_t; } while (0)

extern "C" void kernel_launch(void* const* d_in, const int* in_sizes, int n_in,
                              void* d_out, int out_size) {
    const float* x   = (const float*)d_in[0];
    const float* gnw = (const float*)d_in[1];
    const float* gnb = (const float*)d_in[2];
    const float* wq  = (const float*)d_in[3];
    const float* bq  = (const float*)d_in[4];
    const float* wk  = (const float*)d_in[5];
    const float* bk  = (const float*)d_in[6];
    const float* wv  = (const float*)d_in[7];
    const float* bv  = (const float*)d_in[8];
    const float* wo  = (const float*)d_in[9];
    const float* bo  = (const float*)d_in[10];
    float* out = (float*)d_out;

    static bool attr_done = false;
    if (!attr_done) {
        cudaFuncSetAttribute(mma_gemm<0>, cudaFuncAttributeMaxDynamicSharedMemorySize, SMEM_TOTAL);
        cudaFuncSetAttribute(mma_gemm<1>, cudaFuncAttributeMaxDynamicSharedMemorySize, SMEM_TOTAL);
        cudaFuncSetAttribute(mma_gemm<2>, cudaFuncAttributeMaxDynamicSharedMemorySize, SMEM_TOTAL);
        attr_done = true;
    }

    __nv_bfloat16 *xn,*qkv,*vwo,*vwt,*pun,*wqkvT,*woT;
    float *rsum, *bqkv;
    SYM(xn,  g_xn);      SYM(qkv, g_qkv);
    SYM(vwo, g_vwo);     SYM(vwt, g_vwt);   SYM(pun, g_pun);
    SYM(rsum, g_rowsum); SYM(bqkv, g_bqkv);
    SYM(wqkvT, g_wqkvT); SYM(woT, g_woT);

    const size_t LQKV = (size_t)LSEQ * QKVN;
    const size_t LC   = (size_t)LSEQ * CDIM;
    const size_t LL   = (size_t)LSEQ * LSEQ;
    const float attn_scale = 1.f / sqrtf((float)CDIM);

    // 1) GroupNorm -> bf16 xn ; setup
    gn_stats_kernel<<<BATCH * GROUPS, 256>>>(x);
    gn_norm_bf16<<<8192, 256>>>(x, gnw, gnb);
    setup_kernel<<<BLTOT/256, 256>>>(bq, bk, bv);

    // 2) transpose weights
    dim3 tw(32, 8);
    dim3 gw(CDIM/32, CDIM/32, 1);
    transpose_f2b<<<gw, tw>>>(wq, wqkvT,               CDIM, CDIM);
    transpose_f2b<<<gw, tw>>>(wk, wqkvT + CDIM*CDIM,   CDIM, CDIM);
    transpose_f2b<<<gw, tw>>>(wv, wqkvT + 2*CDIM*CDIM, CDIM, CDIM);
    transpose_f2b<<<gw, tw>>>(wo, woT, CDIM, CDIM);

    // 3) fused QKV projection: [16384,512] x [1536,512]^T -> [16384,1536]
    dim3 grid_qkv(QKVN/BN, BLTOT/BM, 1);
    mma_gemm<1><<<grid_qkv, 512, SMEM_TOTAL>>>(xn, wqkvT, nullptr, qkv, nullptr,
        CDIM, CDIM, CDIM, QKVN, 0, 0, 0, 1.f, bqkv, nullptr);

    // 4) VWo = V @ Wo^T : [16384,512] (A = v slice of qkv, strided)
    dim3 grid_vw(CDIM/BN, BLTOT/BM, 1);
    mma_gemm<1><<<grid_vw, 512, SMEM_TOTAL>>>(qkv + 2*CDIM, woT, nullptr, vwo, nullptr,
        CDIM, QKVN, CDIM, CDIM, 0, 0, 0, 1.f, nullptr, nullptr);

    // 5) (VWo)^T per batch: vwt[b][c][l]
    transpose_b2b<<<dim3(CDIM/32, LSEQ/32, BATCH), tw>>>(
        vwo, vwt, LSEQ, CDIM, LC, LC);

    // 6) unnormalized P = exp(scale*Q@K^T - SHIFT), accumulate row sums
    dim3 grid_s(LSEQ/BN, LSEQ/BM, BATCH);
    mma_gemm<2><<<grid_s, 512, SMEM_TOTAL>>>(qkv, qkv + CDIM, nullptr, pun, rsum,
        CDIM, QKVN, QKVN, LSEQ, LQKV, LQKV, LL, attn_scale, nullptr, nullptr);

    // 7) out = (P_un @ VWo) / rowsum + bo + residual   (final, fp32)
    dim3 grid_pv(CDIM/BN, LSEQ/BM, BATCH);
    mma_gemm<0><<<grid_pv, 512, SMEM_TOTAL>>>(pun, vwt, out, nullptr, rsum,
        LSEQ, LSEQ, LSEQ, CDIM, LL, LC, LC, 1.f, bo, x);
}

// round 12
// speedup vs baseline: 1.1310x; 1.0570x over previous
#include <cuda_runtime.h>
#include <cuda_bf16.h>
#include <math.h>
#include <stdint.h>

#define BATCH  4
#define LSEQ   4096
#define CDIM   512
#define QKVN   (3*CDIM)
#define BLTOT  (BATCH*LSEQ)
#define GROUPS 32
#define EPS_GN 1e-6f
#define EXP_SHIFT 20.0f
#define LOG2E 1.4426950408889634f

// ---- mma.sync GEMM tiling: 256 threads, 8 warps (4m x 2n), warp tile 32x64,
// ---- 2 CTAs/SM for epilogue/barrier overlap ----
#define BM 128
#define BN 128
#define BK 32
#define ROWB    80                     // SMEM row stride bytes (32 bf16 + 8 skew)
#define A_TILE_B (BM*ROWB)             // 10240 B
#define B_TILE_B (BN*ROWB)             // 10240 B
#define STAGE_B  (A_TILE_B + B_TILE_B) // 20480 B
#define NSTAGE 4
#define SMEM_TOTAL (NSTAGE*STAGE_B)    // 81920 B  (x2 CTAs = 160 KB/SM)

// ---------------------------------------------------------------------------
// Scratch (static device globals)
// ---------------------------------------------------------------------------
#define DEVBUF static __device__ __align__(16)
DEVBUF __nv_bfloat16 g_xn  [(size_t)BLTOT*CDIM];
DEVBUF __nv_bfloat16 g_qkv [(size_t)BLTOT*QKVN];      // [B*L][1536] q|k|v
DEVBUF __nv_bfloat16 g_vwo [(size_t)BLTOT*CDIM];      // V @ Wo  [B*L][C]
DEVBUF __nv_bfloat16 g_vwt [(size_t)BLTOT*CDIM];      // (V@Wo)^T [B][C][L]
DEVBUF __nv_bfloat16 g_pun [(size_t)BATCH*LSEQ*LSEQ]; // 134 MB unnormalized probs
DEVBUF float         g_rowsum[BLTOT];
DEVBUF __nv_bfloat16 g_wqkvT[QKVN*CDIM];              // [1536][512] K-major
DEVBUF __nv_bfloat16 g_woT[CDIM*CDIM];
DEVBUF float         g_bqkv[QKVN];
static __device__ float g_mean[BATCH*GROUPS];
static __device__ float g_rstd[BATCH*GROUPS];

// ---------------------------------------------------------------------------
// PTX helpers
// ---------------------------------------------------------------------------
__device__ __forceinline__ uint32_t smem_u32(const void* p) {
    uint32_t a;
    asm("{ .reg .u64 t; cvta.to.shared.u64 t, %1; cvt.u32.u64 %0, t; }" : "=r"(a) : "l"(p));
    return a;
}
__device__ __forceinline__ void cp16(uint32_t dst, const void* src) {
    asm volatile("cp.async.cg.shared.global [%0], [%1], 16;" :: "r"(dst), "l"(src));
}
#define CP_COMMIT()  asm volatile("cp.async.commit_group;" ::: "memory")
#define CP_WAIT2()   asm volatile("cp.async.wait_group 2;" ::: "memory")
#define CP_WAITALL() asm volatile("cp.async.wait_all;" ::: "memory")

__device__ __forceinline__ void ldsm4(uint32_t* r, uint32_t addr) {
    asm volatile("ldmatrix.sync.aligned.m8n8.x4.shared.b16 {%0,%1,%2,%3}, [%4];"
        : "=r"(r[0]), "=r"(r[1]), "=r"(r[2]), "=r"(r[3]) : "r"(addr));
}
__device__ __forceinline__ void mma16816(float* c, const uint32_t* a, const uint32_t* b) {
    asm volatile("mma.sync.aligned.m16n8k16.row.col.f32.bf16.bf16.f32 "
        "{%0,%1,%2,%3}, {%4,%5,%6,%7}, {%8,%9}, {%0,%1,%2,%3};"
        : "+f"(c[0]), "+f"(c[1]), "+f"(c[2]), "+f"(c[3])
        : "r"(a[0]), "r"(a[1]), "r"(a[2]), "r"(a[3]), "r"(b[0]), "r"(b[1]));
}
__device__ __forceinline__ uint32_t pack_bf16(float a, float b) {
    return (uint32_t)__bfloat16_as_ushort(__float2bfloat16(a)) |
           ((uint32_t)__bfloat16_as_ushort(__float2bfloat16(b)) << 16);
}

// ---------------------------------------------------------------------------
// GroupNorm stats
// ---------------------------------------------------------------------------
__global__ void __launch_bounds__(256) gn_stats_kernel(const float* __restrict__ x) {
    int b = blockIdx.x / GROUPS, g = blockIdx.x % GROUPS;
    const float* base = x + (size_t)b * LSEQ * CDIM + g * 16;
    float s = 0.f, s2 = 0.f;
    for (int l = threadIdx.x; l < LSEQ; l += 256) {
        const float4* p = (const float4*)(base + (size_t)l * CDIM);
        #pragma unroll
        for (int j = 0; j < 4; ++j) {
            float4 v = p[j];
            s  += v.x + v.y + v.z + v.w;
            s2 += v.x*v.x + v.y*v.y + v.z*v.z + v.w*v.w;
        }
    }
    __shared__ float sh1[256], sh2[256];
    sh1[threadIdx.x] = s; sh2[threadIdx.x] = s2;
    __syncthreads();
    for (int st = 128; st > 0; st >>= 1) {
        if (threadIdx.x < st) { sh1[threadIdx.x] += sh1[threadIdx.x+st]; sh2[threadIdx.x] += sh2[threadIdx.x+st]; }
        __syncthreads();
    }
    if (threadIdx.x == 0) {
        const float inv = 1.f / (float)(LSEQ * 16);
        float m = sh1[0] * inv;
        g_mean[blockIdx.x] = m;
        g_rstd[blockIdx.x] = rsqrtf(sh2[0]*inv - m*m + EPS_GN);
    }
}

// ---------------------------------------------------------------------------
// Normalize + affine -> bf16 xn
// ---------------------------------------------------------------------------
__global__ void __launch_bounds__(256) gn_norm_bf16(const float* __restrict__ x,
                                                    const float* __restrict__ w,
                                                    const float* __restrict__ bb) {
    size_t i = ((size_t)blockIdx.x * 256 + threadIdx.x) * 4;
    int c = (int)(i & (CDIM - 1));
    int b = (int)(i >> 21);
    int gidx = b * GROUPS + (c >> 4);
    float m = g_mean[gidx], r = g_rstd[gidx];
    float4 v  = *(const float4*)(x + i);
    float4 gw = *(const float4*)(w + c);
    float4 gb = *(const float4*)(bb + c);
    uint2 hv;
    hv.x = pack_bf16((v.x-m)*r*gw.x + gb.x, (v.y-m)*r*gw.y + gb.y);
    hv.y = pack_bf16((v.z-m)*r*gw.z + gb.z, (v.w-m)*r*gw.w + gb.w);
    *(uint2*)(g_xn + i) = hv;
}

// ---------------------------------------------------------------------------
// Transpose fp32 -> bf16 (weights) into K-major [n][k]
// ---------------------------------------------------------------------------
__global__ void transpose_f2b(const float* __restrict__ in,
                              __nv_bfloat16* __restrict__ oh,
                              int rows, int cols) {
    __shared__ float t[32][33];
    int c0 = blockIdx.x * 32, r0 = blockIdx.y * 32;
    for (int dy = threadIdx.y; dy < 32; dy += 8)
        t[dy][threadIdx.x] = in[(size_t)(r0 + dy) * cols + c0 + threadIdx.x];
    __syncthreads();
    for (int dy = threadIdx.y; dy < 32; dy += 8)
        oh[(size_t)(c0 + dy) * rows + r0 + threadIdx.x] = __float2bfloat16(t[threadIdx.x][dy]);
}

// ---------------------------------------------------------------------------
// Transpose bf16 -> bf16: out[z][c][r] = in[z][r][c]
// ---------------------------------------------------------------------------
__global__ void transpose_b2b(const __nv_bfloat16* __restrict__ in,
                              __nv_bfloat16* __restrict__ oh,
                              int rows, int ldIn, size_t strideIn, size_t strideOut) {
    __shared__ unsigned short t[32][33];
    int c0 = blockIdx.x * 32, r0 = blockIdx.y * 32, z = blockIdx.z;
    const __nv_bfloat16* I = in + (size_t)z * strideIn;
    for (int dy = threadIdx.y; dy < 32; dy += 8)
        t[dy][threadIdx.x] = __bfloat16_as_ushort(I[(size_t)(r0 + dy) * ldIn + c0 + threadIdx.x]);
    __syncthreads();
    for (int dy = threadIdx.y; dy < 32; dy += 8) {
        size_t o = (size_t)z * strideOut + (size_t)(c0 + dy) * rows + r0 + threadIdx.x;
        oh[o] = __ushort_as_bfloat16(t[threadIdx.x][dy]);
    }
}

// ---------------------------------------------------------------------------
// Setup: zero rowsum + combined qkv bias
// ---------------------------------------------------------------------------
__global__ void setup_kernel(const float* bq, const float* bk, const float* bv) {
    int t = blockIdx.x * 256 + threadIdx.x;
    if (t < BLTOT) g_rowsum[t] = 0.f;
    if (t < CDIM) {
        g_bqkv[t]          = bq[t];
        g_bqkv[t + CDIM]   = bk[t];
        g_bqkv[t + 2*CDIM] = bv[t];
    }
}

// ---------------------------------------------------------------------------
// bf16 GEMM via mma.sync: D[M,N] = A @ B^T variants.
//   OUTMODE 0: fp32 out, x (1/rowsum[row]), +bias, +resid  (final P@VWo)
//   OUTMODE 1: bf16 out, optional +bias                    (QKV / VWo)
//   OUTMODE 2: bf16 exp(alpha*s - SHIFT) out + rowsum      (scores)
// 256 threads, warps 4(m) x 2(n), warp tile 32x64, 4-stage cp.async, 2 CTAs/SM.
// ---------------------------------------------------------------------------
__device__ __forceinline__ void load_stage(
    uint32_t sbase,
    const __nv_bfloat16* __restrict__ A, const __nv_bfloat16* __restrict__ B,
    int row0, int col0, int kk, int ldA, int ldB, int tid)
{
    #pragma unroll
    for (int j = 0; j < 2; ++j) {      // A: 128 rows x 32 cols = 512 cp16
        int idx = tid + 256*j;
        int r = idx >> 2, k16 = idx & 3;
        cp16(sbase + (uint32_t)(r*ROWB + k16*16),
             A + (size_t)(row0 + r) * ldA + kk + k16*8);
    }
    #pragma unroll
    for (int j = 0; j < 2; ++j) {      // B: 128 rows x 32 cols = 512 cp16
        int idx = tid + 256*j;
        int r = idx >> 2, k16 = idx & 3;
        cp16(sbase + A_TILE_B + (uint32_t)(r*ROWB + k16*16),
             B + (size_t)(col0 + r) * ldB + kk + k16*8);
    }
}

template<int OUTMODE>
__global__ void __launch_bounds__(256, 2) mma_gemm(
    const __nv_bfloat16* __restrict__ A, const __nv_bfloat16* __restrict__ B,
    float* __restrict__ Cf, __nv_bfloat16* __restrict__ Cb,
    float* __restrict__ rowsum,
    int K, int ldA, int ldB, int ldC,
    size_t sA, size_t sB, size_t sC,
    float alpha, const float* __restrict__ bias, const float* __restrict__ resid)
{
    extern __shared__ __align__(128) char smem[];
    const uint32_t sb0 = smem_u32(smem);
    const int tid = threadIdx.x;
    const int lane = tid & 31, wid = tid >> 5;
    const int wm = wid & 3, wn = wid >> 2;        // warps 4(m) x 2(n)
    const int row0 = blockIdx.y * BM;
    const int col0 = blockIdx.x * BN;
    A += sA * blockIdx.z; B += sB * blockIdx.z;
    const size_t zC = sC * blockIdx.z;
    float* rsumz = rowsum ? rowsum + (size_t)blockIdx.z * LSEQ : nullptr;

    const int g = lane >> 3, r = lane & 7;
    const uint32_t aoff = (uint32_t)((wm*32 + (g&1)*8 + r) * ROWB + (g>>1)*16);
    const uint32_t boff = (uint32_t)((wn*64 + (g>>1)*8 + r) * ROWB + (g&1)*16);

    float acc[2][8][4];
    #pragma unroll
    for (int a1 = 0; a1 < 2; ++a1)
        #pragma unroll
        for (int a2 = 0; a2 < 8; ++a2)
            #pragma unroll
            for (int a3 = 0; a3 < 4; ++a3) acc[a1][a2][a3] = 0.f;

    const int nch = K / BK;
    load_stage(sb0,             A, B, row0, col0, 0,    ldA, ldB, tid); CP_COMMIT();
    load_stage(sb0 + STAGE_B,   A, B, row0, col0, BK,   ldA, ldB, tid); CP_COMMIT();
    load_stage(sb0 + 2*STAGE_B, A, B, row0, col0, 2*BK, ldA, ldB, tid); CP_COMMIT();

    for (int i = 0; i < nch; ++i) {
        CP_WAIT2();
        __syncthreads();
        const int nxt = i + 3;
        if (nxt < nch)
            load_stage(sb0 + (uint32_t)((nxt & 3) * STAGE_B),
                       A, B, row0, col0, nxt * BK, ldA, ldB, tid);
        CP_COMMIT();

        const uint32_t sb = sb0 + (uint32_t)((i & 3) * STAGE_B);
        #pragma unroll
        for (int ks = 0; ks < 2; ++ks) {
            uint32_t ah[2][4], bh[4][4];
            #pragma unroll
            for (int mf = 0; mf < 2; ++mf)
                ldsm4(ah[mf], sb + aoff + (uint32_t)(mf*(16*ROWB) + ks*32));
            #pragma unroll
            for (int nf = 0; nf < 4; ++nf)
                ldsm4(bh[nf], sb + A_TILE_B + boff + (uint32_t)(nf*(16*ROWB) + ks*32));
            #pragma unroll
            for (int mf = 0; mf < 2; ++mf)
                #pragma unroll
                for (int nf = 0; nf < 4; ++nf)
                    #pragma unroll
                    for (int n8 = 0; n8 < 2; ++n8)
                        mma16816(acc[mf][nf*2 + n8], ah[mf], &bh[nf][n8*2]);
        }
    }

    // ---- epilogue ----
    float rs[2][2];
    float* srow = (float*)smem;
    if (OUTMODE == 2) {
        rs[0][0] = rs[0][1] = rs[1][0] = rs[1][1] = 0.f;
        CP_WAITALL();
        __syncthreads();
        if (tid < BM) srow[tid] = 0.f;
        __syncthreads();
    }

    const float a2 = alpha * LOG2E;
    const float s2 = EXP_SHIFT * LOG2E;

    float inv0[2], inv1[2];
    if (OUTMODE == 0) {
        #pragma unroll
        for (int mf = 0; mf < 2; ++mf) {
            int rl = row0 + wm*32 + mf*16 + (lane >> 2);
            inv0[mf] = 1.f / rsumz[rl];
            inv1[mf] = 1.f / rsumz[rl + 8];
        }
    }

    #pragma unroll
    for (int mf = 0; mf < 2; ++mf) {
        #pragma unroll
        for (int nf = 0; nf < 4; ++nf) {
            #pragma unroll
            for (int n8 = 0; n8 < 2; ++n8) {
                float* c = acc[mf][nf*2 + n8];
                const int col = col0 + wn*64 + nf*16 + n8*8 + 2*(lane & 3);
                const int rlo = row0 + wm*32 + mf*16 + (lane >> 2);
                const size_t o0 = zC + (size_t)rlo * ldC + col;
                const size_t o1 = zC + (size_t)(rlo + 8) * ldC + col;
                if (OUTMODE == 2) {
                    float e0 = exp2f(fmaf(c[0], a2, -s2));
                    float e1 = exp2f(fmaf(c[1], a2, -s2));
                    float e2 = exp2f(fmaf(c[2], a2, -s2));
                    float e3 = exp2f(fmaf(c[3], a2, -s2));
                    rs[mf][0] += e0 + e1;
                    rs[mf][1] += e2 + e3;
                    *(uint32_t*)(Cb + o0) = pack_bf16(e0, e1);
                    *(uint32_t*)(Cb + o1) = pack_bf16(e2, e3);
                } else if (OUTMODE == 0) {
                    float b0 = bias[col], b1 = bias[col+1];
                    float2 r0v = *(const float2*)(resid + o0);
                    float2 r1v = *(const float2*)(resid + o1);
                    float v0 = fmaf(c[0], inv0[mf], b0 + r0v.x);
                    float v1 = fmaf(c[1], inv0[mf], b1 + r0v.y);
                    float v2 = fmaf(c[2], inv1[mf], b0 + r1v.x);
                    float v3 = fmaf(c[3], inv1[mf], b1 + r1v.y);
                    *(float2*)(Cf + o0) = make_float2(v0, v1);
                    *(float2*)(Cf + o1) = make_float2(v2, v3);
                } else {
                    float v0 = c[0], v1 = c[1], v2 = c[2], v3 = c[3];
                    if (bias) {
                        float b0 = bias[col], b1 = bias[col+1];
                        v0 += b0; v1 += b1; v2 += b0; v3 += b1;
                    }
                    *(uint32_t*)(Cb + o0) = pack_bf16(v0, v1);
                    *(uint32_t*)(Cb + o1) = pack_bf16(v2, v3);
                }
            }
        }
    }

    if (OUTMODE == 2) {
        #pragma unroll
        for (int mf = 0; mf < 2; ++mf)
            #pragma unroll
            for (int h = 0; h < 2; ++h) {
                rs[mf][h] += __shfl_xor_sync(0xffffffffu, rs[mf][h], 1);
                rs[mf][h] += __shfl_xor_sync(0xffffffffu, rs[mf][h], 2);
            }
        if ((lane & 3) == 0) {
            int lr = wm*32 + (lane >> 2);
            #pragma unroll
            for (int mf = 0; mf < 2; ++mf) {
                atomicAdd(&srow[lr + mf*16],     rs[mf][0]);
                atomicAdd(&srow[lr + mf*16 + 8], rs[mf][1]);
            }
        }
        __syncthreads();
        if (tid < BM) atomicAdd(&rsumz[row0 + tid], srow[tid]);
    }
}

// ---------------------------------------------------------------------------
// Launch
// ---------------------------------------------------------------------------
#define SYM(p, s) do { void* _t = nullptr; cudaGetSymbolAddress(&_t, s); p = (decltype(p))_t; } while (0)

extern "C" void kernel_launch(void* const* d_in, const int* in_sizes, int n_in,
                              void* d_out, int out_size) {
    const float* x   = (const float*)d_in[0];
    const float* gnw = (const float*)d_in[1];
    const float* gnb = (const float*)d_in[2];
    const float* wq  = (const float*)d_in[3];
    const float* bq  = (const float*)d_in[4];
    const float* wk  = (const float*)d_in[5];
    const float* bk  = (const float*)d_in[6];
    const float* wv  = (const float*)d_in[7];
    const float* bv  = (const float*)d_in[8];
    const float* wo  = (const float*)d_in[9];
    const float* bo  = (const float*)d_in[10];
    float* out = (float*)d_out;

    static bool attr_done = false;
    if (!attr_done) {
        cudaFuncSetAttribute(mma_gemm<0>, cudaFuncAttributeMaxDynamicSharedMemorySize, SMEM_TOTAL);
        cudaFuncSetAttribute(mma_gemm<1>, cudaFuncAttributeMaxDynamicSharedMemorySize, SMEM_TOTAL);
        cudaFuncSetAttribute(mma_gemm<2>, cudaFuncAttributeMaxDynamicSharedMemorySize, SMEM_TOTAL);
        attr_done = true;
    }

    __nv_bfloat16 *xn,*qkv,*vwo,*vwt,*pun,*wqkvT,*woT;
    float *rsum, *bqkv;
    SYM(xn,  g_xn);      SYM(qkv, g_qkv);
    SYM(vwo, g_vwo);     SYM(vwt, g_vwt);   SYM(pun, g_pun);
    SYM(rsum, g_rowsum); SYM(bqkv, g_bqkv);
    SYM(wqkvT, g_wqkvT); SYM(woT, g_woT);

    const size_t LQKV = (size_t)LSEQ * QKVN;
    const size_t LC   = (size_t)LSEQ * CDIM;
    const size_t LL   = (size_t)LSEQ * LSEQ;
    const float attn_scale = 1.f / sqrtf((float)CDIM);

    // 1) GroupNorm -> bf16 xn ; setup
    gn_stats_kernel<<<BATCH * GROUPS, 256>>>(x);
    gn_norm_bf16<<<8192, 256>>>(x, gnw, gnb);
    setup_kernel<<<BLTOT/256, 256>>>(bq, bk, bv);

    // 2) transpose weights
    dim3 tw(32, 8);
    dim3 gw(CDIM/32, CDIM/32, 1);
    transpose_f2b<<<gw, tw>>>(wq, wqkvT,               CDIM, CDIM);
    transpose_f2b<<<gw, tw>>>(wk, wqkvT + CDIM*CDIM,   CDIM, CDIM);
    transpose_f2b<<<gw, tw>>>(wv, wqkvT + 2*CDIM*CDIM, CDIM, CDIM);
    transpose_f2b<<<gw, tw>>>(wo, woT, CDIM, CDIM);

    // 3) fused QKV projection: [16384,512] x [1536,512]^T -> [16384,1536]
    dim3 grid_qkv(QKVN/BN, BLTOT/BM, 1);
    mma_gemm<1><<<grid_qkv, 256, SMEM_TOTAL>>>(xn, wqkvT, nullptr, qkv, nullptr,
        CDIM, CDIM, CDIM, QKVN, 0, 0, 0, 1.f, bqkv, nullptr);

    // 4) VWo = V @ Wo^T : [16384,512] (A = v slice of qkv, strided)
    dim3 grid_vw(CDIM/BN, BLTOT/BM, 1);
    mma_gemm<1><<<grid_vw, 256, SMEM_TOTAL>>>(qkv + 2*CDIM, woT, nullptr, vwo, nullptr,
        CDIM, QKVN, CDIM, CDIM, 0, 0, 0, 1.f, nullptr, nullptr);

    // 5) (VWo)^T per batch: vwt[b][c][l]
    transpose_b2b<<<dim3(CDIM/32, LSEQ/32, BATCH), tw>>>(
        vwo, vwt, LSEQ, CDIM, LC, LC);

    // 6) unnormalized P = exp(scale*Q@K^T - SHIFT), accumulate row sums
    dim3 grid_s(LSEQ/BN, LSEQ/BM, BATCH);
    mma_gemm<2><<<grid_s, 256, SMEM_TOTAL>>>(qkv, qkv + CDIM, nullptr, pun, rsum,
        CDIM, QKVN, QKVN, LSEQ, LQKV, LQKV, LL, attn_scale, nullptr, nullptr);

    // 7) out = (P_un @ VWo) / rowsum + bo + residual   (final, fp32)
    dim3 grid_pv(CDIM/BN, LSEQ/BM, BATCH);
    mma_gemm<0><<<grid_pv, 256, SMEM_TOTAL>>>(pun, vwt, out, nullptr, rsum,
        LSEQ, LSEQ, LSEQ, CDIM, LL, LC, LC, 1.f, bo, x);
}